// round 8
// baseline (speedup 1.0000x reference)
#include <cuda_runtime.h>

// MedianPool2d 3x3, stride 1, reflect pad (1,1,1,1)
// float32 [16, 3, 512, 512] -> same shape.
//
// 4(W) x 4(H) outputs per thread. Vertical stage on FMA pipe via packed f32x2
// arithmetic compare-exchange; horizontal combine scalar FMNMX (ALU pipe).
// Halos via warp shuffle (lane 0/31 fix up with predicated loads; reflect
// folded into the address). 32-bit offsets. The 4-row tile amortizes the
// ~100-instruction per-thread overhead over 16 outputs instead of 8.

#define W 512
#define H 512

typedef unsigned long long u64;
typedef unsigned int u32;

__device__ __forceinline__ u64 pk(float x, float y) {
    u64 r; asm("mov.b64 %0, {%1, %2};" : "=l"(r) : "f"(x), "f"(y)); return r;
}
__device__ __forceinline__ float2 upk(u64 v) {
    float2 f; asm("mov.b64 {%0, %1}, %2;" : "=f"(f.x), "=f"(f.y) : "l"(v)); return f;
}

// packed compare-exchange on 2 fp32 lanes: lo=min, hi=max
__device__ __forceinline__ void cex2(u64 a, u64 b, u64& lo, u64& hi) {
    const u64 n1 = 0xBF800000BF800000ULL;
    const u64 hf = 0x3F0000003F000000ULL;
    const u64 nh = 0xBF000000BF000000ULL;
    u64 s, d, k, h;
    asm("add.rn.f32x2 %0, %1, %2;" : "=l"(s) : "l"(a), "l"(b));
    asm("fma.rn.f32x2 %0, %1, %2, %3;" : "=l"(d) : "l"(b), "l"(n1), "l"(a)); // a-b
    k = d & 0x7FFFFFFF7FFFFFFFULL;                                           // |a-b|
    asm("mul.rn.f32x2 %0, %1, %2;" : "=l"(h) : "l"(s), "l"(hf));             // 0.5(a+b)
    asm("fma.rn.f32x2 %0, %1, %2, %3;" : "=l"(lo) : "l"(k), "l"(nh), "l"(h));
    asm("fma.rn.f32x2 %0, %1, %2, %3;" : "=l"(hi) : "l"(k), "l"(hf), "l"(h));
}

__device__ __forceinline__ float med3(float a, float b, float c) {
    return fmaxf(fminf(a, b), fminf(fmaxf(a, b), c));
}

struct Row3 { u64 a, b, c; };   // packed columns (1,2) (3,4) (0,5)

__device__ __forceinline__ void emit_row(const Row3& pl, const Row3& ph,
                                         const Row3& t,
                                         float* __restrict__ dst) {
    float4 res;
    u64 loa, mia, hia, loc, mic, hic, tm;
    cex2(pl.a, t.a, loa, tm);
    cex2(ph.a, tm, mia, hia);
    cex2(pl.c, t.c, loc, tm);
    cex2(ph.c, tm, mic, hic);

    float2 la = upk(loa), lc = upk(loc);
    float2 ma = upk(mia), mc = upk(mic);
    float2 ha = upk(hia), hc = upk(hic);

    float sA  = fmaxf(la.x, la.y);
    float tA  = fminf(ha.x, ha.y);
    float q0A = fminf(ma.x, ma.y), q1A = fmaxf(ma.x, ma.y);

    u64 lob, mib, hib;
    cex2(pl.b, t.b, lob, tm);
    cex2(ph.b, tm, mib, hib);
    float2 lb = upk(lob), mb = upk(mib), hb = upk(hib);

    res.x = med3(fmaxf(lc.x, sA),
                 fmaxf(q0A, fminf(q1A, mc.x)),
                 fminf(hc.x, tA));
    res.y = med3(fmaxf(sA, lb.x),
                 fmaxf(q0A, fminf(q1A, mb.x)),
                 fminf(tA, hb.x));

    float sB  = fmaxf(lb.x, lb.y);
    float tB  = fminf(hb.x, hb.y);
    float q0B = fminf(mb.x, mb.y), q1B = fmaxf(mb.x, mb.y);

    res.z = med3(fmaxf(la.y, sB),
                 fmaxf(q0B, fminf(q1B, ma.y)),
                 fminf(ha.y, tB));
    res.w = med3(fmaxf(sB, lc.y),
                 fmaxf(q0B, fminf(q1B, mc.y)),
                 fminf(tB, hc.y));

    *reinterpret_cast<float4*>(dst) = res;
}

__global__ __launch_bounds__(128, 9)
void median3x3_kernel(const float* __restrict__ x, float* __restrict__ out) {
    const int tid   = threadIdx.x;        // 0..127
    const int lane  = tid & 31;
    const int h0    = blockIdx.x << 2;    // 4 output rows per block
    const u32 plane = blockIdx.y;         // 0..47
    const int w0    = tid << 2;

    const u32 base = plane * (u32)(H * W);

    // frame rows f0..f5 = input rows h0-1 .. h0+4 (reflected at edges)
    const int hr0 = (h0 == 0)     ? 1     : h0 - 1;
    const int hr5 = (h0 + 4 >= H) ? H - 2 : h0 + 4;

    u32 o[6];
    o[0] = base + (u32)hr0 * W;
    o[1] = base + (u32)h0 * W;
    o[2] = o[1] + W;
    o[3] = o[2] + W;
    o[4] = o[3] + W;
    o[5] = base + (u32)hr5 * W;

    // 6 vector loads up front
    float4 q[6];
#pragma unroll
    for (int r = 0; r < 6; r++)
        q[r] = *reinterpret_cast<const float4*>(x + o[r] + w0);

    // halo exchange via shuffle; lane 0/31 fix up with loads (reflect folded
    // into the address: w0==0 -> col 1 ; w0+4==W -> col W-2)
    float lv[6], rv[6];
#pragma unroll
    for (int r = 0; r < 6; r++) {
        lv[r] = __shfl_up_sync(0xffffffffu, q[r].w, 1);
        rv[r] = __shfl_down_sync(0xffffffffu, q[r].x, 1);
    }
    if (lane == 0) {
        const u32 wlc = (w0 == 0) ? 1u : (u32)(w0 - 1);
#pragma unroll
        for (int r = 0; r < 6; r++) lv[r] = x[o[r] + wlc];
    }
    if (lane == 31) {
        const u32 wrc = (w0 + 4 == W) ? (u32)(W - 2) : (u32)(w0 + 4);
#pragma unroll
        for (int r = 0; r < 6; r++) rv[r] = x[o[r] + wrc];
    }

    Row3 f[6];
#pragma unroll
    for (int r = 0; r < 6; r++) {
        f[r].a = pk(q[r].x, q[r].y);
        f[r].b = pk(q[r].z, q[r].w);
        f[r].c = pk(lv[r], rv[r]);
    }

    float* od = out + o[1] + w0;

    // pairA = sort(f1,f2): serves output rows 0 (third f0) and 1 (third f3)
    {
        Row3 pl, ph;
        cex2(f[1].a, f[2].a, pl.a, ph.a);
        cex2(f[1].b, f[2].b, pl.b, ph.b);
        cex2(f[1].c, f[2].c, pl.c, ph.c);
        emit_row(pl, ph, f[0], od);
        emit_row(pl, ph, f[3], od + W);
    }
    // pairB = sort(f3,f4): serves output rows 2 (third f2) and 3 (third f5)
    {
        Row3 pl, ph;
        cex2(f[3].a, f[4].a, pl.a, ph.a);
        cex2(f[3].b, f[4].b, pl.b, ph.b);
        cex2(f[3].c, f[4].c, pl.c, ph.c);
        emit_row(pl, ph, f[2], od + 2 * W);
        emit_row(pl, ph, f[5], od + 3 * W);
    }
}

extern "C" void kernel_launch(void* const* d_in, const int* in_sizes, int n_in,
                              void* d_out, int out_size) {
    const float* x = (const float*)d_in[0];
    float* out = (float*)d_out;
    dim3 grid(H / 4, 48);    // 128 row-quads x 48 planes
    dim3 block(128);
    median3x3_kernel<<<grid, block>>>(x, out);
}